// round 14
// baseline (speedup 1.0000x reference)
#include <cuda_runtime.h>
#include <cuda_bf16.h>
#include <math.h>
#include <stdint.h>

typedef unsigned long long ull;

// ---------------- scratch (static device globals; no allocation) ----------------
__device__ float g_pre[2u * 512u * 32u * 512u];   // [dir][t][b][c] 64MB
__device__ float g_hs[512u * 32u * 1024u];        // [t][b][dir*512+c] 64MB
__device__ unsigned int g_bar[16 * 32];           // per-(dir,grp) counters, 128B apart

// ---------------- f32x2 helpers ----------------
__device__ __forceinline__ ull ffma2(ull a, ull b, ull c) {
    ull d;
    asm("fma.rn.f32x2 %0, %1, %2, %3;" : "=l"(d) : "l"(a), "l"(b), "l"(c));
    return d;
}
__device__ __forceinline__ ull pack2(float x) {
    ull d;
    asm("mov.b64 %0, {%1, %1};" : "=l"(d) : "f"(x));
    return d;
}
__device__ __forceinline__ ull packab(float a, float b) {
    ull d;
    asm("mov.b64 %0, {%1, %2};" : "=l"(d) : "f"(a), "f"(b));
    return d;
}
__device__ __forceinline__ float2 unpack2(ull v) {
    float2 r;
    asm("mov.b64 {%0, %1}, %2;" : "=f"(r.x), "=f"(r.y) : "l"(v));
    return r;
}

// =================================================================================
// Kernel 1: pre-projection GEMM v3
//   BM=64, BN=128, BK=8, 256 threads, 4m x 8n micro-tile (N-paired acc[4][4]),
//   occupancy 3 CTAs/SM. grid = (8 n-tiles, 256 m-tiles) = 2048 CTAs.
// =================================================================================
__global__ __launch_bounds__(256, 3) void pre_gemm(
    const float* __restrict__ X,
    const float* __restrict__ Wf, const float* __restrict__ bf,
    const float* __restrict__ Wb, const float* __restrict__ bb)
{
    __shared__ float As[2][8][68];
    __shared__ float Bs[2][8][136];

    if (blockIdx.x == 0 && blockIdx.y == 0 && threadIdx.x < 16)
        g_bar[threadIdx.x * 32] = 0u;

    const int tid = threadIdx.x;
    const int m0 = blockIdx.y * 64;
    const int n0 = blockIdx.x * 128;
    const int dir = n0 >> 9;
    const int c0 = n0 & 511;
    const float* Bmat = dir ? Wb : Wf;
    const float* bias = dir ? bb : bf;

    // A loader: threads 0..127, one float4 along K of one M-row
    const int ar  = tid >> 1;                 // 0..127 (used if tid<128 -> 0..63)
    const int akq = (tid & 1) * 4;
    const int am  = m0 + (ar & 63);
    const float* Arow = X + ((size_t)(am & 31) * 512 + (size_t)(am >> 5)) * 512;

    // B loader: all 256 threads, one float4
    const int bkk = tid >> 5;
    const int bnq = (tid & 31) * 4;

    const int ty = tid >> 4;                  // 0..15 -> m micro base ty*4
    const int tx = tid & 15;                  // 0..15 -> n micro base tx*8

    ull acc[4][4];   // [m][n-pair]
    #pragma unroll
    for (int i = 0; i < 4; ++i)
        #pragma unroll
        for (int j = 0; j < 4; ++j) acc[i][j] = 0ull;

    {
        float4 bv = *(const float4*)(Bmat + (size_t)bkk * 512 + c0 + bnq);
        *(float4*)&Bs[0][bkk][bnq] = bv;
        if (tid < 128) {
            float4 av = *(const float4*)(Arow + akq);
            As[0][akq + 0][ar] = av.x;
            As[0][akq + 1][ar] = av.y;
            As[0][akq + 2][ar] = av.z;
            As[0][akq + 3][ar] = av.w;
        }
    }
    __syncthreads();

    int buf = 0;
    for (int k0 = 0; k0 < 512; k0 += 8) {
        float4 av, bv;
        const bool more = (k0 + 8 < 512);
        if (more) {
            bv = *(const float4*)(Bmat + (size_t)(k0 + 8 + bkk) * 512 + c0 + bnq);
            if (tid < 128)
                av = *(const float4*)(Arow + k0 + 8 + akq);
        }

        #pragma unroll
        for (int k = 0; k < 8; ++k) {
            float4 aA = *(const float4*)&As[buf][k][ty * 4];
            ulonglong2 b01 = *(const ulonglong2*)&Bs[buf][k][tx * 8];
            ulonglong2 b23 = *(const ulonglong2*)&Bs[buf][k][tx * 8 + 4];
            ull ad[4];
            ad[0] = pack2(aA.x); ad[1] = pack2(aA.y);
            ad[2] = pack2(aA.z); ad[3] = pack2(aA.w);
            #pragma unroll
            for (int m = 0; m < 4; ++m) {
                acc[m][0] = ffma2(ad[m], b01.x, acc[m][0]);
                acc[m][1] = ffma2(ad[m], b01.y, acc[m][1]);
                acc[m][2] = ffma2(ad[m], b23.x, acc[m][2]);
                acc[m][3] = ffma2(ad[m], b23.y, acc[m][3]);
            }
        }

        if (more) {
            int nb = buf ^ 1;
            *(float4*)&Bs[nb][bkk][bnq] = bv;
            if (tid < 128) {
                As[nb][akq + 0][ar] = av.x;
                As[nb][akq + 1][ar] = av.y;
                As[nb][akq + 2][ar] = av.z;
                As[nb][akq + 3][ar] = av.w;
            }
            __syncthreads();
            buf = nb;
        }
    }

    // epilogue: acc[m] holds 8 consecutive output columns cg..cg+7
    const int cg = c0 + tx * 8;
    float4 bl = *(const float4*)(bias + cg);
    float4 bh = *(const float4*)(bias + cg + 4);
    #pragma unroll
    for (int m = 0; m < 4; ++m) {
        float2 p0 = unpack2(acc[m][0]);
        float2 p1 = unpack2(acc[m][1]);
        float2 p2 = unpack2(acc[m][2]);
        float2 p3 = unpack2(acc[m][3]);
        int gm = m0 + ty * 4 + m;
        int tt = gm >> 5, bb2 = gm & 31;
        float* dst = g_pre + ((size_t)dir * 512 + tt) * 16384 + (size_t)bb2 * 512 + cg;
        float4 o0, o1;
        o0.x = p0.x + bl.x; o0.y = p0.y + bl.y;
        o0.z = p1.x + bl.z; o0.w = p1.y + bl.w;
        o1.x = p2.x + bh.x; o1.y = p2.y + bh.y;
        o1.z = p3.x + bh.z; o1.w = p3.y + bh.w;
        *(float4*)dst = o0;
        *(float4*)(dst + 4) = o1;
    }
}

// =================================================================================
// Kernel 2: persistent bidirectional recurrence (R13 verbatim — measured best)
// =================================================================================
__global__ __launch_bounds__(512) void recur_kernel(
    const float* __restrict__ Wf, const float* __restrict__ Wb)
{
    __shared__ float s_h[4 * 520];      // [4 batches][512+8]
    __shared__ float s_red[8 * 256];    // [ks][b*64+c]

    const int tid = threadIdx.x;
    const int bx  = blockIdx.x;
    const int dir = bx & 1;
    const int grp = (bx >> 1) & 7;          // batch group 0..7 (4 batches)
    const int sl  = bx >> 4;                // col slice 0..7 (64 cols)
    const int c0  = sl * 64;
    const int bgl = grp * 4;
    const float* W = dir ? Wb : Wf;

    const int c  = tid & 63;
    const int ks = tid >> 6;

    ull wreg[16][2];
    #pragma unroll
    for (int j = 0; j < 16; ++j) {
        int k = ks * 64 + j * 4;
        const float* wp = W + (size_t)(512 + k) * 512 + c0 + c;
        wreg[j][0] = packab(wp[0],    wp[512]);
        wreg[j][1] = packab(wp[1024], wp[1536]);
    }

    const int sb   = tid >> 7;
    const int soff = (tid & 127) * 4;

    const int rb = tid >> 6;
    const int rc = tid & 63;

    unsigned int* bar = &g_bar[(dir * 8 + grp) * 32];

    float pre = 0.f;
    {
        const int t0 = dir ? 511 : 0;
        if (tid < 256)
            pre = __ldcg(&g_pre[((size_t)dir * 512 + t0) * 16384 +
                                (size_t)(bgl + rb) * 512 + c0 + rc]);
    }

    for (int s = 0; s < 512; ++s) {
        const int t = dir ? (511 - s) : s;

        float hval = 0.f;
        if (s == 0) {
            if (tid < 256) hval = tanhf(pre);
        } else {
            const int tp = dir ? (t + 1) : (t - 1);
            const float* hbase = g_hs + (size_t)tp * 32 * 1024 +
                                 (size_t)bgl * 1024 + dir * 512;

            float4 v0 = __ldcg((const float4*)(hbase + sb * 1024 + soff));
            *(float4*)&s_h[sb * 520 + soff] = v0;
            __syncthreads();

            ull acc[4] = {0ull, 0ull, 0ull, 0ull};
            #pragma unroll
            for (int b = 0; b < 4; ++b) {
                const ulonglong2* hp = (const ulonglong2*)&s_h[b * 520 + ks * 64];
                #pragma unroll
                for (int j = 0; j < 16; ++j) {
                    ulonglong2 h2 = hp[j];
                    acc[b] = ffma2(h2.x, wreg[j][0], acc[b]);
                    acc[b] = ffma2(h2.y, wreg[j][1], acc[b]);
                }
            }
            #pragma unroll
            for (int b = 0; b < 4; ++b) {
                float2 p = unpack2(acc[b]);
                s_red[ks * 256 + b * 64 + c] = p.x + p.y;
            }
            __syncthreads();

            if (tid < 256) {
                float sum = pre;
                #pragma unroll
                for (int k8 = 0; k8 < 8; ++k8) sum += s_red[k8 * 256 + tid];
                hval = tanhf(sum);
            }
        }

        if (tid < 256)
            __stcg(&g_hs[((size_t)t * 32 + bgl + rb) * 1024 +
                         dir * 512 + c0 + rc], hval);

        if (s < 511) {
            __syncthreads();
            if (tid == 0)
                asm volatile("red.release.gpu.global.add.u32 [%0], 1;"
                             :: "l"(bar) : "memory");
            const int tn = dir ? (510 - s) : (s + 1);
            float npre = 0.f;
            if (tid < 256)
                npre = __ldcg(&g_pre[((size_t)dir * 512 + tn) * 16384 +
                                     (size_t)(bgl + rb) * 512 + c0 + rc]);
            if ((tid & 31) == 0) {
                const unsigned target = (unsigned)(s + 1) * 8u;
                unsigned v;
                int spins = 0;
                for (;;) {
                    asm volatile("ld.acquire.gpu.global.u32 %0, [%1];"
                                 : "=r"(v) : "l"(bar) : "memory");
                    if (v >= target) break;
                    if (++spins > 2048) __nanosleep(64);
                }
            }
            __syncwarp();
            pre = npre;
        }
    }
}

// =================================================================================
// Kernel 3: output GEMM v3
//   BM=64, BN=64, BK=8, 256 threads, 4m x 4n micro-tile (acc[4][2]),
//   occupancy 3. grid = (8 n-tiles, 256 m-tiles) = 2048 CTAs.
// =================================================================================
__global__ __launch_bounds__(256, 3) void out_gemm(
    const float* __restrict__ Wo, const float* __restrict__ bo,
    float* __restrict__ out)
{
    __shared__ float As[2][8][68];
    __shared__ float Bs[2][8][72];

    const int tid = threadIdx.x;
    const int m0 = blockIdx.y * 64;
    const int n0 = blockIdx.x * 64;

    // A loader: threads 0..127
    const int ar  = tid >> 1;
    const int akq = (tid & 1) * 4;
    const float* Arow = g_hs + (size_t)(m0 + (ar & 63)) * 1024;

    // B loader: threads 128..255 (8k x 64n = 128 float4)
    const int btid = tid - 128;
    const int bkk = btid >> 4;               // 0..7
    const int bnq = (btid & 15) * 4;         // 0..60

    const int ty = tid >> 4;                  // m micro base ty*4
    const int tx = tid & 15;                  // n micro base tx*4

    ull acc[4][2];
    #pragma unroll
    for (int i = 0; i < 4; ++i) { acc[i][0] = 0ull; acc[i][1] = 0ull; }

    {
        if (tid < 128) {
            float4 av = *(const float4*)(Arow + akq);
            As[0][akq + 0][ar] = av.x;
            As[0][akq + 1][ar] = av.y;
            As[0][akq + 2][ar] = av.z;
            As[0][akq + 3][ar] = av.w;
        } else {
            float4 bv = *(const float4*)(Wo + (size_t)bkk * 512 + n0 + bnq);
            *(float4*)&Bs[0][bkk][bnq] = bv;
        }
    }
    __syncthreads();

    int buf = 0;
    for (int k0 = 0; k0 < 1024; k0 += 8) {
        float4 av, bv;
        const bool more = (k0 + 8 < 1024);
        if (more) {
            if (tid < 128)
                av = *(const float4*)(Arow + k0 + 8 + akq);
            else
                bv = *(const float4*)(Wo + (size_t)(k0 + 8 + bkk) * 512 + n0 + bnq);
        }

        #pragma unroll
        for (int k = 0; k < 8; ++k) {
            float4 aA = *(const float4*)&As[buf][k][ty * 4];
            ulonglong2 b01 = *(const ulonglong2*)&Bs[buf][k][tx * 4];
            ull ad[4];
            ad[0] = pack2(aA.x); ad[1] = pack2(aA.y);
            ad[2] = pack2(aA.z); ad[3] = pack2(aA.w);
            #pragma unroll
            for (int m = 0; m < 4; ++m) {
                acc[m][0] = ffma2(ad[m], b01.x, acc[m][0]);
                acc[m][1] = ffma2(ad[m], b01.y, acc[m][1]);
            }
        }

        if (more) {
            int nb = buf ^ 1;
            if (tid < 128) {
                As[nb][akq + 0][ar] = av.x;
                As[nb][akq + 1][ar] = av.y;
                As[nb][akq + 2][ar] = av.z;
                As[nb][akq + 3][ar] = av.w;
            } else {
                *(float4*)&Bs[nb][bkk][bnq] = bv;
            }
            __syncthreads();
            buf = nb;
        }
    }

    const int og = n0 + tx * 4;
    float4 bl = *(const float4*)(bo + og);
    #pragma unroll
    for (int m = 0; m < 4; ++m) {
        float2 p0 = unpack2(acc[m][0]);
        float2 p1 = unpack2(acc[m][1]);
        int gm = m0 + ty * 4 + m;
        int tt = gm >> 5, bb2 = gm & 31;
        float* dst = out + ((size_t)bb2 * 512 + tt) * 512 + og;
        float4 o0;
        o0.x = p0.x + bl.x; o0.y = p0.y + bl.y;
        o0.z = p1.x + bl.z; o0.w = p1.y + bl.w;
        *(float4*)dst = o0;
    }
}

// =================================================================================
extern "C" void kernel_launch(void* const* d_in, const int* in_sizes, int n_in,
                              void* d_out, int out_size)
{
    const float* X  = (const float*)d_in[0];
    const float* Wf = (const float*)d_in[1];
    const float* bf = (const float*)d_in[2];
    const float* Wb = (const float*)d_in[3];
    const float* bb = (const float*)d_in[4];
    const float* Wo = (const float*)d_in[5];
    const float* bo = (const float*)d_in[6];
    float* out = (float*)d_out;

    pre_gemm<<<dim3(8, 256), 256>>>(X, Wf, bf, Wb, bb);
    recur_kernel<<<128, 512>>>(Wf, Wb);
    out_gemm<<<dim3(8, 256), 256>>>(Wo, bo, out);
}

// round 15
// speedup vs baseline: 1.1420x; 1.1420x over previous
#include <cuda_runtime.h>
#include <cuda_bf16.h>
#include <math.h>
#include <stdint.h>

typedef unsigned long long ull;

// ---------------- scratch (static device globals; no allocation) ----------------
__device__ float g_pre[2u * 512u * 32u * 512u];   // [dir][t][b][c] 64MB
__device__ float g_hs[512u * 32u * 1024u];        // [t][b][dir*512+c] 64MB
__device__ unsigned int g_bar[16 * 32];           // per-(dir,grp) counters, 128B apart

// ---------------- f32x2 helpers ----------------
__device__ __forceinline__ ull ffma2(ull a, ull b, ull c) {
    ull d;
    asm("fma.rn.f32x2 %0, %1, %2, %3;" : "=l"(d) : "l"(a), "l"(b), "l"(c));
    return d;
}
__device__ __forceinline__ ull pack2(float x) {
    ull d;
    asm("mov.b64 %0, {%1, %1};" : "=l"(d) : "f"(x));
    return d;
}
__device__ __forceinline__ ull packab(float a, float b) {
    ull d;
    asm("mov.b64 %0, {%1, %2};" : "=l"(d) : "f"(a), "f"(b));
    return d;
}
__device__ __forceinline__ float2 unpack2(ull v) {
    float2 r;
    asm("mov.b64 {%0, %1}, %2;" : "=f"(r.x), "=f"(r.y) : "l"(v));
    return r;
}

// =================================================================================
// Kernel 1: pre-projection GEMM (R12 verbatim: 128x128 tile, N-paired acc)
// =================================================================================
__global__ __launch_bounds__(256, 2) void pre_gemm(
    const float* __restrict__ X,
    const float* __restrict__ Wf, const float* __restrict__ bf,
    const float* __restrict__ Wb, const float* __restrict__ bb)
{
    __shared__ float As[2][8][132];
    __shared__ float Bs[2][8][136];

    if (blockIdx.x == 0 && blockIdx.y == 0 && threadIdx.x < 16)
        g_bar[threadIdx.x * 32] = 0u;

    const int tid = threadIdx.x;
    const int m0 = blockIdx.y * 128;
    const int n0 = blockIdx.x * 128;
    const int dir = n0 >> 9;
    const int c0 = n0 & 511;
    const float* Bmat = dir ? Wb : Wf;
    const float* bias = dir ? bb : bf;

    const int ar  = tid >> 1;
    const int akq = (tid & 1) * 4;
    const int am  = m0 + ar;
    const float* Arow = X + ((size_t)(am & 31) * 512 + (size_t)(am >> 5)) * 512;

    const int bkk = tid >> 5;
    const int bnq = (tid & 31) * 4;

    const int ty = tid >> 4;
    const int tx = tid & 15;

    ull acc[8][4];   // [m][n-pair]
    #pragma unroll
    for (int i = 0; i < 8; ++i)
        #pragma unroll
        for (int j = 0; j < 4; ++j) acc[i][j] = 0ull;

    {
        float4 av = *(const float4*)(Arow + akq);
        float4 bv = *(const float4*)(Bmat + (size_t)bkk * 512 + c0 + bnq);
        As[0][akq + 0][ar] = av.x;
        As[0][akq + 1][ar] = av.y;
        As[0][akq + 2][ar] = av.z;
        As[0][akq + 3][ar] = av.w;
        *(float4*)&Bs[0][bkk][bnq] = bv;
    }
    __syncthreads();

    int buf = 0;
    for (int k0 = 0; k0 < 512; k0 += 8) {
        float4 av, bv;
        const bool more = (k0 + 8 < 512);
        if (more) {
            av = *(const float4*)(Arow + k0 + 8 + akq);
            bv = *(const float4*)(Bmat + (size_t)(k0 + 8 + bkk) * 512 + c0 + bnq);
        }

        #pragma unroll
        for (int k = 0; k < 8; ++k) {
            float4 aA = *(const float4*)&As[buf][k][ty * 8];
            float4 aB = *(const float4*)&As[buf][k][ty * 8 + 4];
            ulonglong2 b01 = *(const ulonglong2*)&Bs[buf][k][tx * 8];
            ulonglong2 b23 = *(const ulonglong2*)&Bs[buf][k][tx * 8 + 4];
            ull ad[8];
            ad[0] = pack2(aA.x); ad[1] = pack2(aA.y);
            ad[2] = pack2(aA.z); ad[3] = pack2(aA.w);
            ad[4] = pack2(aB.x); ad[5] = pack2(aB.y);
            ad[6] = pack2(aB.z); ad[7] = pack2(aB.w);
            #pragma unroll
            for (int m = 0; m < 8; ++m) {
                acc[m][0] = ffma2(ad[m], b01.x, acc[m][0]);
                acc[m][1] = ffma2(ad[m], b01.y, acc[m][1]);
                acc[m][2] = ffma2(ad[m], b23.x, acc[m][2]);
                acc[m][3] = ffma2(ad[m], b23.y, acc[m][3]);
            }
        }

        if (more) {
            int nb = buf ^ 1;
            As[nb][akq + 0][ar] = av.x;
            As[nb][akq + 1][ar] = av.y;
            As[nb][akq + 2][ar] = av.z;
            As[nb][akq + 3][ar] = av.w;
            *(float4*)&Bs[nb][bkk][bnq] = bv;
            __syncthreads();
            buf = nb;
        }
    }

    const int cg = c0 + tx * 8;
    float4 bl = *(const float4*)(bias + cg);
    float4 bh = *(const float4*)(bias + cg + 4);
    #pragma unroll
    for (int m = 0; m < 8; ++m) {
        float2 p0 = unpack2(acc[m][0]);
        float2 p1 = unpack2(acc[m][1]);
        float2 p2 = unpack2(acc[m][2]);
        float2 p3 = unpack2(acc[m][3]);
        int gm = m0 + ty * 8 + m;
        int tt = gm >> 5, bb2 = gm & 31;
        float* dst = g_pre + ((size_t)dir * 512 + tt) * 16384 + (size_t)bb2 * 512 + cg;
        float4 o0, o1;
        o0.x = p0.x + bl.x; o0.y = p0.y + bl.y;
        o0.z = p1.x + bl.z; o0.w = p1.y + bl.w;
        o1.x = p2.x + bh.x; o1.y = p2.y + bh.y;
        o1.z = p3.x + bh.z; o1.w = p3.y + bh.w;
        *(float4*)dst = o0;
        *(float4*)(dst + 4) = o1;
    }
}

// =================================================================================
// Kernel 2: persistent bidirectional recurrence (v11 — warp-local duplicate staging)
//   128 CTAs = 2 dirs x 8 batch-groups(4) x 8 col-slices(64), 512 threads.
//   Thread (c 0..63, ks 0..7): compute identical to R13, but each warp stages
//   ONLY its ks-slice (1KB, duplicated by the sibling warp) and uses __syncwarp
//   instead of a CTA-wide stage-sync. Barrier = R13 counter + per-warp detect.
// =================================================================================
__global__ __launch_bounds__(512) void recur_kernel(
    const float* __restrict__ Wf, const float* __restrict__ Wb)
{
    __shared__ float s_h[4 * 520];      // [4 batches][512+8]
    __shared__ float s_red[8 * 256];    // [ks][b*64+c]

    const int tid = threadIdx.x;
    const int bx  = blockIdx.x;
    const int dir = bx & 1;
    const int grp = (bx >> 1) & 7;          // batch group 0..7 (4 batches)
    const int sl  = bx >> 4;                // col slice 0..7 (64 cols)
    const int c0  = sl * 64;
    const int bgl = grp * 4;
    const float* W = dir ? Wb : Wf;

    const int c  = tid & 63;
    const int ks = tid >> 6;

    // Wh column (c0+c), k in [ks*64, ks*64+64) -> 32 f32x2 regs
    ull wreg[16][2];
    #pragma unroll
    for (int j = 0; j < 16; ++j) {
        int k = ks * 64 + j * 4;
        const float* wp = W + (size_t)(512 + k) * 512 + c0 + c;
        wreg[j][0] = packab(wp[0],    wp[512]);
        wreg[j][1] = packab(wp[1024], wp[1536]);
    }

    // warp-local staging map: warp covers its ks-slice (4 rows x 64 cols)
    const int lane = tid & 31;
    const int srow = lane >> 3;             // batch row 0..3
    const int scq  = (lane & 7) * 8;        // float offset within 64-col slice

    // reduce/store map (tid < 256): batch rb, col rc
    const int rb = tid >> 6;
    const int rc = tid & 63;

    unsigned int* bar = &g_bar[(dir * 8 + grp) * 32];

    // first step's pre-activation
    float pre = 0.f;
    {
        const int t0 = dir ? 511 : 0;
        if (tid < 256)
            pre = __ldcg(&g_pre[((size_t)dir * 512 + t0) * 16384 +
                                (size_t)(bgl + rb) * 512 + c0 + rc]);
    }

    for (int s = 0; s < 512; ++s) {
        const int t = dir ? (511 - s) : s;

        float hval = 0.f;
        if (s == 0) {
            if (tid < 256) hval = tanhf(pre);
        } else {
            const int tp = dir ? (t + 1) : (t - 1);

            // warp stages its own 1KB ks-slice (sibling warp duplicates — benign)
            {
                const float* hp2 = g_hs + ((size_t)tp * 32 + bgl + srow) * 1024 +
                                   dir * 512 + ks * 64 + scq;
                float4 v0 = __ldcg((const float4*)hp2);
                float4 v1 = __ldcg((const float4*)(hp2 + 4));
                *(float4*)&s_h[srow * 520 + ks * 64 + scq]     = v0;
                *(float4*)&s_h[srow * 520 + ks * 64 + scq + 4] = v1;
            }
            __syncwarp();   // warp's own staging visible to all its lanes

            // mat-vec partials over this thread's ks-slice (4 batches)
            ull acc[4] = {0ull, 0ull, 0ull, 0ull};
            #pragma unroll
            for (int b = 0; b < 4; ++b) {
                const ulonglong2* hp = (const ulonglong2*)&s_h[b * 520 + ks * 64];
                #pragma unroll
                for (int j = 0; j < 16; ++j) {
                    ulonglong2 h2 = hp[j];
                    acc[b] = ffma2(h2.x, wreg[j][0], acc[b]);
                    acc[b] = ffma2(h2.y, wreg[j][1], acc[b]);
                }
            }
            #pragma unroll
            for (int b = 0; b < 4; ++b) {
                float2 p = unpack2(acc[b]);
                s_red[ks * 256 + b * 64 + c] = p.x + p.y;
            }
            __syncthreads();   // all partials visible before reduce

            if (tid < 256) {
                float sum = pre;
                #pragma unroll
                for (int k8 = 0; k8 < 8; ++k8) sum += s_red[k8 * 256 + tid];
                hval = tanhf(sum);
            }
        }

        if (tid < 256)
            __stcg(&g_hs[((size_t)t * 32 + bgl + rb) * 1024 +
                         dir * 512 + c0 + rc], hval);

        if (s < 511) {
            __syncthreads();   // CTA-HB: h stores before release; also fences s_h/s_red reuse
            if (tid == 0)
                asm volatile("red.release.gpu.global.add.u32 [%0], 1;"
                             :: "l"(bar) : "memory");
            // prefetch next step's pre (independent of the poll)
            const int tn = dir ? (510 - s) : (s + 1);
            float npre = 0.f;
            if (tid < 256)
                npre = __ldcg(&g_pre[((size_t)dir * 512 + tn) * 16384 +
                                     (size_t)(bgl + rb) * 512 + c0 + rc]);
            // warp-autonomous detect
            if ((tid & 31) == 0) {
                const unsigned target = (unsigned)(s + 1) * 8u;
                unsigned v;
                int spins = 0;
                for (;;) {
                    asm volatile("ld.acquire.gpu.global.u32 %0, [%1];"
                                 : "=r"(v) : "l"(bar) : "memory");
                    if (v >= target) break;
                    if (++spins > 2048) __nanosleep(64);
                }
            }
            __syncwarp();      // orders lane0's acquire before this warp's h loads
            pre = npre;
        }
    }
}

// =================================================================================
// Kernel 3: output GEMM (R12 verbatim: 128x128 tile, N-paired acc)
// =================================================================================
__global__ __launch_bounds__(256, 2) void out_gemm(
    const float* __restrict__ Wo, const float* __restrict__ bo,
    float* __restrict__ out)
{
    __shared__ float As[2][8][132];
    __shared__ float Bs[2][8][136];

    const int tid = threadIdx.x;
    const int m0 = blockIdx.y * 128;
    const int n0 = blockIdx.x * 128;

    const int ar  = tid >> 1;
    const int akq = (tid & 1) * 4;
    const float* Arow = g_hs + (size_t)(m0 + ar) * 1024;

    const int bkk = tid >> 5;
    const int bnq = (tid & 31) * 4;

    const int ty = tid >> 4;
    const int tx = tid & 15;

    ull acc[8][4];
    #pragma unroll
    for (int i = 0; i < 8; ++i)
        #pragma unroll
        for (int j = 0; j < 4; ++j) acc[i][j] = 0ull;

    {
        float4 av = *(const float4*)(Arow + akq);
        float4 bv = *(const float4*)(Wo + (size_t)bkk * 512 + n0 + bnq);
        As[0][akq + 0][ar] = av.x;
        As[0][akq + 1][ar] = av.y;
        As[0][akq + 2][ar] = av.z;
        As[0][akq + 3][ar] = av.w;
        *(float4*)&Bs[0][bkk][bnq] = bv;
    }
    __syncthreads();

    int buf = 0;
    for (int k0 = 0; k0 < 1024; k0 += 8) {
        float4 av, bv;
        const bool more = (k0 + 8 < 1024);
        if (more) {
            av = *(const float4*)(Arow + k0 + 8 + akq);
            bv = *(const float4*)(Wo + (size_t)(k0 + 8 + bkk) * 512 + n0 + bnq);
        }

        #pragma unroll
        for (int k = 0; k < 8; ++k) {
            float4 aA = *(const float4*)&As[buf][k][ty * 8];
            float4 aB = *(const float4*)&As[buf][k][ty * 8 + 4];
            ulonglong2 b01 = *(const ulonglong2*)&Bs[buf][k][tx * 8];
            ulonglong2 b23 = *(const ulonglong2*)&Bs[buf][k][tx * 8 + 4];
            ull ad[8];
            ad[0] = pack2(aA.x); ad[1] = pack2(aA.y);
            ad[2] = pack2(aA.z); ad[3] = pack2(aA.w);
            ad[4] = pack2(aB.x); ad[5] = pack2(aB.y);
            ad[6] = pack2(aB.z); ad[7] = pack2(aB.w);
            #pragma unroll
            for (int m = 0; m < 8; ++m) {
                acc[m][0] = ffma2(ad[m], b01.x, acc[m][0]);
                acc[m][1] = ffma2(ad[m], b01.y, acc[m][1]);
                acc[m][2] = ffma2(ad[m], b23.x, acc[m][2]);
                acc[m][3] = ffma2(ad[m], b23.y, acc[m][3]);
            }
        }

        if (more) {
            int nb = buf ^ 1;
            As[nb][akq + 0][ar] = av.x;
            As[nb][akq + 1][ar] = av.y;
            As[nb][akq + 2][ar] = av.z;
            As[nb][akq + 3][ar] = av.w;
            *(float4*)&Bs[nb][bkk][bnq] = bv;
            __syncthreads();
            buf = nb;
        }
    }

    const int og = n0 + tx * 8;
    float4 bl = *(const float4*)(bo + og);
    float4 bh = *(const float4*)(bo + og + 4);
    #pragma unroll
    for (int m = 0; m < 8; ++m) {
        float2 p0 = unpack2(acc[m][0]);
        float2 p1 = unpack2(acc[m][1]);
        float2 p2 = unpack2(acc[m][2]);
        float2 p3 = unpack2(acc[m][3]);
        int gm = m0 + ty * 8 + m;
        int tt = gm >> 5, bb2 = gm & 31;
        float* dst = out + ((size_t)bb2 * 512 + tt) * 512 + og;
        float4 o0, o1;
        o0.x = p0.x + bl.x; o0.y = p0.y + bl.y;
        o0.z = p1.x + bl.z; o0.w = p1.y + bl.w;
        o1.x = p2.x + bh.x; o1.y = p2.y + bh.y;
        o1.z = p3.x + bh.z; o1.w = p3.y + bh.w;
        *(float4*)dst = o0;
        *(float4*)(dst + 4) = o1;
    }
}

// =================================================================================
extern "C" void kernel_launch(void* const* d_in, const int* in_sizes, int n_in,
                              void* d_out, int out_size)
{
    const float* X  = (const float*)d_in[0];
    const float* Wf = (const float*)d_in[1];
    const float* bf = (const float*)d_in[2];
    const float* Wb = (const float*)d_in[3];
    const float* bb = (const float*)d_in[4];
    const float* Wo = (const float*)d_in[5];
    const float* bo = (const float*)d_in[6];
    float* out = (float*)d_out;

    pre_gemm<<<dim3(8, 128), 256>>>(X, Wf, bf, Wb, bb);
    recur_kernel<<<128, 512>>>(Wf, Wb);
    out_gemm<<<dim3(4, 128), 256>>>(Wo, bo, out);
}